// round 15
// baseline (speedup 1.0000x reference)
#include <cuda_runtime.h>
#include <cuda_bf16.h>
#include <cuda_fp16.h>
#include <cstdint>
#include <math.h>

#define BATCH 2
#define S_LEN 2048
#define HID   4096
#define NH    32
#define NKV   8
#define HD    128
#define QKVN  6144          // Q 4096 | K 1024 | V 1024
#define VOFF  5120          // Q_SIZE + KV_SIZE
#define KDIM  4096          // GEMM K (reduction) for both projections

// ---------------- scratch (no allocation allowed -> device globals) ----------
__device__ float g_qkv [BATCH * S_LEN * QKVN];      // qkv projection output (fp32)
__device__ float g_invfreq[64];

// fp16 split operands for the tensor-core GEMMs (A exact as hi+lo; B hi only)
__device__ __half g_Ahi [4096 * 4096];              // A hi (hidden; then attn out)
__device__ __half g_Alo [4096 * 4096];              // A lo
__device__ __half g_Bqh [QKVN * 4096];              // w_qkv^T fp16  [N=6144][K=4096]
__device__ __half g_Boh [4096 * 4096];              // w_o^T  fp16   [N=4096][K=4096]

// fp16 attention operands (Q exact hi+lo; K, V single fp16)
__device__ __half g_Qh [BATCH * NH  * S_LEN * HD];  // [b][h][s][d]
__device__ __half g_Ql [BATCH * NH  * S_LEN * HD];
__device__ __half g_Kh [BATCH * NKV * S_LEN * HD];  // [b][kh][s][d]
__device__ __half g_Vh [BATCH * NKV * HD * S_LEN];  // [b][kh][d][s]

// ================= helpers ====================================================
__device__ __forceinline__ uint32_t smem_u32(const void* p) {
    uint32_t a;
    asm("{ .reg .u64 t; cvta.to.shared.u64 t, %1; cvt.u32.u64 %0, t; }" : "=r"(a) : "l"(p));
    return a;
}

#define LDSM_X4(r, addr) \
    asm volatile("ldmatrix.sync.aligned.m8n8.x4.shared.b16 {%0,%1,%2,%3}, [%4];" \
        : "=r"((r)[0]), "=r"((r)[1]), "=r"((r)[2]), "=r"((r)[3]) : "r"(addr))

// fp16 MMA
#define MMAF16(c, a, b0, b1) \
    asm volatile("mma.sync.aligned.m16n8k16.row.col.f32.f16.f16.f32 " \
        "{%0,%1,%2,%3}, {%4,%5,%6,%7}, {%8,%9}, {%0,%1,%2,%3};" \
        : "+f"((c)[0]), "+f"((c)[1]), "+f"((c)[2]), "+f"((c)[3]) \
        : "r"((a)[0]), "r"((a)[1]), "r"((a)[2]), "r"((a)[3]), "r"(b0), "r"(b1))

#define CP_ASYNC16(dst, src) \
    asm volatile("cp.async.cg.shared.global [%0], [%1], 16;" :: "r"(dst), "l"(src))
#define CP_COMMIT() asm volatile("cp.async.commit_group;" ::: "memory")
#define CP_WAIT(n)  asm volatile("cp.async.wait_group %0;" :: "n"(n) : "memory")

__device__ __forceinline__ void split2h(float a, float b, uint32_t& hi, uint32_t& lo) {
    __half ha = __float2half_rn(a), hb = __float2half_rn(b);
    __half la = __float2half_rn(a - __half2float(ha));
    __half lb = __float2half_rn(b - __half2float(hb));
    __half2 H = __halves2half2(ha, hb);
    __half2 L = __halves2half2(la, lb);
    hi = *(uint32_t*)&H;  lo = *(uint32_t*)&L;
}

extern __shared__ char dynsmem[];

// ---------------- inv_freq table ---------------------------------------------
__global__ void init_invfreq_kernel() {
    int i = threadIdx.x;
    if (i < 64) {
        const float LOG2_10000 = 13.28771237954945f;
        g_invfreq[i] = exp2f(-((float)(2 * i) / 128.0f) * LOG2_10000);
    }
}

// ---------------- fp32 -> fp16 hi/lo split (elementwise, float4) --------------
__global__ void __launch_bounds__(256) split_a_kernel(
    const float* __restrict__ X, __half* __restrict__ hi,
    __half* __restrict__ lo, int n4)
{
    int i = blockIdx.x * 256 + threadIdx.x;
    if (i >= n4) return;
    float4 v = ((const float4*)X)[i];
    uint32_t h0, l0, h1, l1;
    split2h(v.x, v.y, h0, l0);
    split2h(v.z, v.w, h1, l1);
    ((uint32_t*)hi)[i * 2]     = h0;
    ((uint32_t*)hi)[i * 2 + 1] = h1;
    ((uint32_t*)lo)[i * 2]     = l0;
    ((uint32_t*)lo)[i * 2 + 1] = l1;
}

// ---------------- W[K,N] fp32 -> Bt[N,K] fp16 (tiled transpose, hi only) ------
__global__ void __launch_bounds__(256) transpose_split_kernel(
    const float* __restrict__ W, __half* __restrict__ bhi, int K, int N)
{
    __shared__ float tile[32][33];
    int tx = threadIdx.x & 31, ty = threadIdx.x >> 5;   // 32 x 8
    int k0 = blockIdx.y * 32, n0 = blockIdx.x * 32;
#pragma unroll
    for (int r = 0; r < 4; r++)
        tile[ty + r * 8][tx] = W[(size_t)(k0 + ty + r * 8) * N + n0 + tx];
    __syncthreads();
#pragma unroll
    for (int r = 0; r < 4; r++) {
        int n = n0 + ty + r * 8;
        int k = k0 + tx;
        bhi[(size_t)n * K + k] = __float2half_rn(tile[tx][ty + r * 8]);
    }
}

// ---------------- mma.sync fp16 2-product GEMM (3-stage, 2 CTAs/SM) -----------
#define GPITCH 80
#define GTSZ   (128 * GPITCH)          // 10240
#define GSTG   (3 * GTSZ)              // 30720 per stage (Ah | Al | Bh)
#define GEMM_SMEM_BYTES (3 * GSTG)     // 92160 -> 2 CTAs = 184320 <= 228KB

__global__ void __launch_bounds__(256, 2) gemm_mma_kernel(
    const __half* __restrict__ Ahi, const __half* __restrict__ Alo,
    const __half* __restrict__ Bh,
    float* __restrict__ C, int Ntot)
{
    const uint32_t sb = smem_u32(dynsmem);
    const int t = threadIdx.x;
    const int wid = t >> 5, lane = t & 31;
    const int bm = blockIdx.y, bn = blockIdx.x;
    const int wm = (wid >> 2) * 64;
    const int wn = (wid & 3) * 32;

    const __half* gsrc[3] = {
        Ahi + (size_t)(bm * 128) * KDIM,
        Alo + (size_t)(bm * 128) * KDIM,
        Bh  + (size_t)(bn * 128) * KDIM };

    const int lrow = t >> 1;
    const int lq   = (t & 1) * 2;

    auto load_chunk = [&](int c, int s) {
        uint32_t base = sb + s * GSTG + lrow * GPITCH + lq * 16;
#pragma unroll
        for (int tens = 0; tens < 3; tens++) {
            const __half* src = gsrc[tens] + (size_t)lrow * KDIM + c * 32 + lq * 8;
            uint32_t d = base + tens * GTSZ;
            CP_ASYNC16(d, src);
            CP_ASYNC16(d + 16, src + 8);
        }
    };

    float acc[4][4][4];
#pragma unroll
    for (int a = 0; a < 4; a++)
#pragma unroll
        for (int b = 0; b < 4; b++)
#pragma unroll
            for (int c = 0; c < 4; c++) acc[a][b][c] = 0.f;

    const int NCH = KDIM / 32;   // 128 chunks

    load_chunk(0, 0);
    CP_COMMIT();
    load_chunk(1, 1);
    CP_COMMIT();

    for (int i = 0; i < NCH; i++) {
        const int s = i % 3;
        if (i + 1 < NCH) CP_WAIT(1); else CP_WAIT(0);
        __syncthreads();
        if (i + 2 < NCH) {
            load_chunk(i + 2, (i + 2) % 3);
            CP_COMMIT();
        }

        const uint32_t sA = sb + s * GSTG;
        const uint32_t sB = sA + 2 * GTSZ;

#pragma unroll
        for (int ks = 0; ks < 2; ks++) {
            const int k0b = ks * 32;
            uint32_t b_hi[2][4];
#pragma unroll
            for (int p = 0; p < 2; p++) {
                uint32_t bd = sB + (uint32_t)(wn + p * 16 + ((lane >> 4) << 3) + (lane & 7)) * GPITCH
                            + k0b + (((lane >> 3) & 1) << 4);
                LDSM_X4(b_hi[p], bd);
            }
#pragma unroll
            for (int mt = 0; mt < 4; mt++) {
                uint32_t ah[4], al[4];
                uint32_t ad = sA + (uint32_t)(wm + mt * 16 + (lane & 15)) * GPITCH
                            + k0b + ((lane >> 4) << 4);
                LDSM_X4(ah, ad);
                LDSM_X4(al, ad + GTSZ);
#pragma unroll
                for (int nt = 0; nt < 4; nt++) {
                    const int p = nt >> 1, hh = (nt & 1) * 2;
                    MMAF16(acc[mt][nt], ah, b_hi[p][hh], b_hi[p][hh + 1]);
                }
#pragma unroll
                for (int nt = 0; nt < 4; nt++) {
                    const int p = nt >> 1, hh = (nt & 1) * 2;
                    MMAF16(acc[mt][nt], al, b_hi[p][hh], b_hi[p][hh + 1]);
                }
            }
        }
    }

#pragma unroll
    for (int mt = 0; mt < 4; mt++)
#pragma unroll
        for (int nt = 0; nt < 4; nt++) {
            int row = bm * 128 + wm + mt * 16 + (lane >> 2);
            int col = bn * 128 + wn + nt * 8 + (lane & 3) * 2;
            float2 v0 = make_float2(acc[mt][nt][0], acc[mt][nt][1]);
            float2 v1 = make_float2(acc[mt][nt][2], acc[mt][nt][3]);
            *(float2*)(C + (size_t)row * Ntot + col)       = v0;
            *(float2*)(C + (size_t)(row + 8) * Ntot + col) = v1;
        }
}

// ---------------- RoPE (NeoX): Q -> fp16 hi/lo ; K -> fp16 (single) -----------
__global__ void rope_split_kernel(const float* __restrict__ qkv,
                                  const int*   __restrict__ positions)
{
    int idx = blockIdx.x * 256 + threadIdx.x;
    int i  = idx & 63;
    int s  = (idx >> 6) & (S_LEN - 1);
    int r  = idx >> 17;          // b*40 + hh
    int hh = r % 40;
    int b  = r / 40;

    float pos = (float)positions[b * S_LEN + s];
    float ang = pos * g_invfreq[i];
    float sn, cs;
    sincosf(ang, &sn, &cs);

    if (hh < 32) {
        const float* src = qkv + ((size_t)(b * S_LEN + s)) * QKVN + hh * HD;
        float x1 = src[i], x2 = src[i + 64];
        float y1 = x1 * cs - x2 * sn;
        float y2 = x2 * cs + x1 * sn;
        size_t base = ((size_t)(b * NH + hh) * S_LEN + s) * HD;
        __half h1 = __float2half_rn(y1);
        __half h2 = __float2half_rn(y2);
        g_Qh[base + i]      = h1;
        g_Qh[base + i + 64] = h2;
        g_Ql[base + i]      = __float2half_rn(y1 - __half2float(h1));
        g_Ql[base + i + 64] = __float2half_rn(y2 - __half2float(h2));
    } else {
        int kh = hh - 32;
        const float* src = qkv + ((size_t)(b * S_LEN + s)) * QKVN + HID + kh * HD;
        float x1 = src[i], x2 = src[i + 64];
        float y1 = x1 * cs - x2 * sn;
        float y2 = x2 * cs + x1 * sn;
        size_t base = ((size_t)(b * NKV + kh) * S_LEN + s) * HD;
        g_Kh[base + i]      = __float2half_rn(y1);
        g_Kh[base + i + 64] = __float2half_rn(y2);
    }
}

// ---------------- V: [s][d] fp32 -> [d][s] fp16 (tiled transpose, hi only) ----
__global__ void __launch_bounds__(256) v_split_kernel(const float* __restrict__ qkv)
{
    __shared__ float tile[32][33];
    int tx = threadIdx.x & 31, ty = threadIdx.x >> 5;   // 32 x 8
    int s0 = blockIdx.x * 32, d0 = blockIdx.y * 32;
    int slab = blockIdx.z;                               // b*NKV + kh
    int b = slab / NKV, kh = slab % NKV;

    const float* src = qkv + (size_t)(b * S_LEN) * QKVN + VOFF + kh * HD;
#pragma unroll
    for (int r = 0; r < 4; r++)
        tile[ty + r * 8][tx] = src[(size_t)(s0 + ty + r * 8) * QKVN + d0 + tx];
    __syncthreads();
#pragma unroll
    for (int r = 0; r < 4; r++) {
        int d = d0 + ty + r * 8;
        int s = s0 + tx;
        size_t o = ((size_t)(b * NKV + kh) * HD + d) * S_LEN + s;
        g_Vh[o] = __float2half_rn(tile[tx][ty + r * 8]);
    }
}

// ---------------- mma.sync fp16 2-product flash attention ---------------------
// Single-stage KV (no double buffer) -> smem 103KB -> 2 CTAs/SM.
// QK^T: Q exact (hi+lo fp16) x K fp16 ; PV: P exact (hi+lo fp16) x V fp16.
#define AQ_PITCH 272     // 256B row + 16B pad
#define AK_PITCH 272
#define AV_PITCH 144     // 128B row + 16B pad
#define SQ_BYTES (128 * AQ_PITCH)            // 34816
#define SK_BYTES (64  * AK_PITCH)            // 17408
#define SV_BYTES (128 * AV_PITCH)            // 18432
#define ATT_SMEM_BYTES (2 * SQ_BYTES + SK_BYTES + SV_BYTES)  // 105472 -> 2 CTAs/SM

__global__ void __launch_bounds__(256, 2) attn_mma_kernel(
    __half* __restrict__ Ohi, __half* __restrict__ Olo)
{
    const int qt = (int)gridDim.x - 1 - (int)blockIdx.x;  // heavy tiles first
    const int h  = blockIdx.y;
    const int b  = blockIdx.z;
    const int kh = h >> 2;

    const uint32_t sb  = smem_u32(dynsmem);
    const uint32_t sQh = sb;
    const uint32_t sQl = sQh + SQ_BYTES;
    const uint32_t sKh = sQl + SQ_BYTES;
    const uint32_t sVh = sKh + SK_BYTES;

    const int t = threadIdx.x;
    const int wid = t >> 5, lane = t & 31;
    const int wm = wid * 16;

    const __half* kb0 = g_Kh + ((size_t)(b * NKV + kh) * S_LEN) * HD;
    const __half* vb0 = g_Vh + ((size_t)(b * NKV + kh) * HD) * S_LEN;

    // ---- load Q tile (once) ----
    {
        const __half* q0 = g_Qh + ((size_t)(b * NH + h) * S_LEN + qt * 128) * HD;
        const __half* q1 = g_Ql + ((size_t)(b * NH + h) * S_LEN + qt * 128) * HD;
#pragma unroll
        for (int u = 0; u < 8; u++) {
            int id = t + u * 256;            // 2048 ids: 128 rows x 16 chunks
            int row = id >> 4, ch = id & 15;
            uint32_t d = row * AQ_PITCH + ch * 16;
            CP_ASYNC16(sQh + d, q0 + (size_t)row * HD + ch * 8);
            CP_ASYNC16(sQl + d, q1 + (size_t)row * HD + ch * 8);
        }
        CP_COMMIT();
    }

    float acc[16][4];
#pragma unroll
    for (int n = 0; n < 16; n++)
#pragma unroll
        for (int c = 0; c < 4; c++) acc[n][c] = 0.f;
    float m0 = -1e30f, m1 = -1e30f, l0 = 0.f, l1 = 0.f;

    const float SC = 0.08838834764831843f;
    const int nkt = 2 * qt + 2;

    for (int kt = 0; kt < nkt; kt++) {
        // ---- load K/V tile kt (single stage; prior compute finished reading) --
#pragma unroll
        for (int u = 0; u < 4; u++) {
            int id = t + u * 256;            // 1024: 64 rows x 16 chunks (K)
            int row = id >> 4, ch = id & 15;
            CP_ASYNC16(sKh + row * AK_PITCH + ch * 16,
                       kb0 + (size_t)(kt * 64 + row) * HD + ch * 8);
        }
#pragma unroll
        for (int u = 0; u < 4; u++) {
            int id = t + u * 256;            // 1024: 128 rows x 8 chunks (V)
            int row = id >> 3, ch = id & 7;
            CP_ASYNC16(sVh + row * AV_PITCH + ch * 16,
                       vb0 + (size_t)row * S_LEN + kt * 64 + ch * 8);
        }
        CP_COMMIT();
        CP_WAIT(0);
        __syncthreads();

        // ---- scores: S = Q K^T (64 cols), 2-product (Qh+Ql) x Kh ----
        float sc4[8][4];
#pragma unroll
        for (int n = 0; n < 8; n++)
#pragma unroll
            for (int c = 0; c < 4; c++) sc4[n][c] = 0.f;

#pragma unroll
        for (int dc = 0; dc < 8; dc++) {
            const int k0b = dc * 32;
            uint32_t ah[4], al[4];
            uint32_t qa = sQh + (uint32_t)(wm + (lane & 15)) * AQ_PITCH + k0b + ((lane >> 4) << 4);
            LDSM_X4(ah, qa);
            LDSM_X4(al, qa + SQ_BYTES);
#pragma unroll
            for (int p = 0; p < 4; p++) {
                uint32_t bh[4];
                uint32_t ka = sKh + (uint32_t)(p * 16 + ((lane >> 4) << 3) + (lane & 7)) * AK_PITCH
                            + k0b + (((lane >> 3) & 1) << 4);
                LDSM_X4(bh, ka);
                MMAF16(sc4[2 * p],     ah, bh[0], bh[1]);
                MMAF16(sc4[2 * p + 1], ah, bh[2], bh[3]);
                MMAF16(sc4[2 * p],     al, bh[0], bh[1]);
                MMAF16(sc4[2 * p + 1], al, bh[2], bh[3]);
            }
        }

        // ---- scale + causal mask (only last two kt tiles need masking) ----
        if (kt >= 2 * qt) {
            const int gr0 = qt * 128 + wm + (lane >> 2);
#pragma unroll
            for (int nt = 0; nt < 8; nt++)
#pragma unroll
                for (int c = 0; c < 4; c++) {
                    int gc = kt * 64 + nt * 8 + ((lane & 3) << 1) + (c & 1);
                    int gr = gr0 + ((c >> 1) << 3);
                    sc4[nt][c] = (gc > gr) ? -1e30f : sc4[nt][c] * SC;
                }
        } else {
#pragma unroll
            for (int nt = 0; nt < 8; nt++)
#pragma unroll
                for (int c = 0; c < 4; c++) sc4[nt][c] *= SC;
        }

        // ---- online softmax (two rows per thread; quad shfl) ----
        float mt0 = -1e30f, mt1 = -1e30f;
#pragma unroll
        for (int nt = 0; nt < 8; nt++) {
            mt0 = fmaxf(mt0, fmaxf(sc4[nt][0], sc4[nt][1]));
            mt1 = fmaxf(mt1, fmaxf(sc4[nt][2], sc4[nt][3]));
        }
        mt0 = fmaxf(mt0, __shfl_xor_sync(0xffffffffu, mt0, 1));
        mt0 = fmaxf(mt0, __shfl_xor_sync(0xffffffffu, mt0, 2));
        mt1 = fmaxf(mt1, __shfl_xor_sync(0xffffffffu, mt1, 1));
        mt1 = fmaxf(mt1, __shfl_xor_sync(0xffffffffu, mt1, 2));
        float mn0 = fmaxf(m0, mt0), mn1 = fmaxf(m1, mt1);
        float es0 = __expf(m0 - mn0), es1 = __expf(m1 - mn1);
        float rs0 = 0.f, rs1 = 0.f;
#pragma unroll
        for (int nt = 0; nt < 8; nt++) {
            sc4[nt][0] = __expf(sc4[nt][0] - mn0);
            sc4[nt][1] = __expf(sc4[nt][1] - mn0);
            sc4[nt][2] = __expf(sc4[nt][2] - mn1);
            sc4[nt][3] = __expf(sc4[nt][3] - mn1);
            rs0 += sc4[nt][0] + sc4[nt][1];
            rs1 += sc4[nt][2] + sc4[nt][3];
        }
        rs0 += __shfl_xor_sync(0xffffffffu, rs0, 1);
        rs0 += __shfl_xor_sync(0xffffffffu, rs0, 2);
        rs1 += __shfl_xor_sync(0xffffffffu, rs1, 1);
        rs1 += __shfl_xor_sync(0xffffffffu, rs1, 2);
        l0 = l0 * es0 + rs0;  m0 = mn0;
        l1 = l1 * es1 + rs1;  m1 = mn1;
#pragma unroll
        for (int n = 0; n < 16; n++) {
            acc[n][0] *= es0;  acc[n][1] *= es0;
            acc[n][2] *= es1;  acc[n][3] *= es1;
        }

        // ---- PV: O += P V ; P exact (hi+lo fp16) x Vh ----
#pragma unroll
        for (int kc = 0; kc < 4; kc++) {
            uint32_t ph[4], pl[4];
            split2h(sc4[2 * kc][0],     sc4[2 * kc][1],     ph[0], pl[0]);
            split2h(sc4[2 * kc][2],     sc4[2 * kc][3],     ph[1], pl[1]);
            split2h(sc4[2 * kc + 1][0], sc4[2 * kc + 1][1], ph[2], pl[2]);
            split2h(sc4[2 * kc + 1][2], sc4[2 * kc + 1][3], ph[3], pl[3]);
#pragma unroll
            for (int dp = 0; dp < 8; dp++) {
                uint32_t vh4[4];
                uint32_t va = sVh + (uint32_t)(dp * 16 + ((lane >> 4) << 3) + (lane & 7)) * AV_PITCH
                            + kc * 32 + (((lane >> 3) & 1) << 4);
                LDSM_X4(vh4, va);
                const int n0 = dp * 2, n1 = dp * 2 + 1;
                MMAF16(acc[n0], ph, vh4[0], vh4[1]);
                MMAF16(acc[n1], ph, vh4[2], vh4[3]);
                MMAF16(acc[n0], pl, vh4[0], vh4[1]);
                MMAF16(acc[n1], pl, vh4[2], vh4[3]);
            }
        }
        __syncthreads();   // all warps done reading K/V before next overwrite
    }

    // ---- epilogue: normalize, split to fp16 hi/lo, write [b*S+s][h*128+d] ----
    const float inv0 = 1.0f / l0, inv1 = 1.0f / l1;
    const size_t row0 = (size_t)(b * S_LEN + qt * 128 + wm + (lane >> 2));
    const int colb = h * HD + ((lane & 3) << 1);
#pragma unroll
    for (int nt = 0; nt < 16; nt++) {
        uint32_t h0, lo0, h1, lo1;
        split2h(acc[nt][0] * inv0, acc[nt][1] * inv0, h0, lo0);
        split2h(acc[nt][2] * inv1, acc[nt][3] * inv1, h1, lo1);
        const size_t o0 = row0 * HID + colb + nt * 8;
        const size_t o1 = (row0 + 8) * HID + colb + nt * 8;
        *(uint32_t*)(Ohi + o0) = h0;
        *(uint32_t*)(Olo + o0) = lo0;
        *(uint32_t*)(Ohi + o1) = h1;
        *(uint32_t*)(Olo + o1) = lo1;
    }
}

// ---------------- launch ------------------------------------------------------
extern "C" void kernel_launch(void* const* d_in, const int* in_sizes, int n_in,
                              void* d_out, int out_size)
{
    const int*   positions = (const int*)  d_in[0];
    const float* hidden    = (const float*)d_in[1];
    const float* w_qkv     = (const float*)d_in[2];
    const float* w_o       = (const float*)d_in[3];
    float*       out       = (float*)d_out;

    static float* qkv_p;
    static __half *ahi, *alo, *bqh, *boh;
    static bool init_done = false;
    if (!init_done) {
        cudaGetSymbolAddress((void**)&qkv_p, g_qkv);
        cudaGetSymbolAddress((void**)&ahi, g_Ahi);
        cudaGetSymbolAddress((void**)&alo, g_Alo);
        cudaGetSymbolAddress((void**)&bqh, g_Bqh);
        cudaGetSymbolAddress((void**)&boh, g_Boh);
        cudaFuncSetAttribute(gemm_mma_kernel,
                             cudaFuncAttributeMaxDynamicSharedMemorySize, GEMM_SMEM_BYTES);
        cudaFuncSetAttribute(attn_mma_kernel,
                             cudaFuncAttributeMaxDynamicSharedMemorySize, ATT_SMEM_BYTES);
        init_done = true;
    }

    const int M = BATCH * S_LEN;   // 4096

    init_invfreq_kernel<<<1, 64>>>();

    // prep: split hidden (fp16 hi/lo), transpose weights (fp16 hi)
    split_a_kernel<<<(M * KDIM / 4 + 255) / 256, 256>>>(hidden, ahi, alo, M * KDIM / 4);
    transpose_split_kernel<<<dim3(QKVN / 32, KDIM / 32), 256>>>(w_qkv, bqh, KDIM, QKVN);
    transpose_split_kernel<<<dim3(HID / 32, KDIM / 32), 256>>>(w_o, boh, KDIM, HID);

    // qkv = hidden @ w_qkv  (fp16 2-product)
    gemm_mma_kernel<<<dim3(QKVN / 128, M / 128), 256, GEMM_SMEM_BYTES>>>(
        ahi, alo, bqh, qkv_p, QKVN);

    // rope + split Q (exact) / K (single); transpose V (single)
    rope_split_kernel<<<(BATCH * 40 * S_LEN * 64) / 256, 256>>>(qkv_p, positions);
    v_split_kernel<<<dim3(S_LEN / 32, HD / 32, BATCH * NKV), 256>>>(qkv_p);

    // flash attention (fp16 2-product, 2 CTAs/SM); writes fp16 hi/lo into A bufs
    attn_mma_kernel<<<dim3(S_LEN / 128, NH, BATCH), 256, ATT_SMEM_BYTES>>>(ahi, alo);

    // out = attn @ w_o  (fp16 2-product)
    gemm_mma_kernel<<<dim3(HID / 128, M / 128), 256, GEMM_SMEM_BYTES>>>(
        ahi, alo, boh, out, HID);
}

// round 16
// speedup vs baseline: 1.5681x; 1.5681x over previous
#include <cuda_runtime.h>
#include <cuda_bf16.h>
#include <cuda_fp16.h>
#include <cstdint>
#include <math.h>

#define BATCH 2
#define S_LEN 2048
#define HID   4096
#define NH    32
#define NKV   8
#define HD    128
#define QKVN  6144          // Q 4096 | K 1024 | V 1024
#define VOFF  5120          // Q_SIZE + KV_SIZE
#define KDIM  4096          // GEMM K (reduction) for both projections

// ---------------- scratch (no allocation allowed -> device globals) ----------
__device__ float g_qkv [BATCH * S_LEN * QKVN];      // qkv projection output (fp32)
__device__ float g_invfreq[64];

// fp16 split operands for the tensor-core GEMMs (A exact as hi+lo; B hi only)
__device__ __half g_Ahi [4096 * 4096];              // A hi (hidden; then attn out)
__device__ __half g_Alo [4096 * 4096];              // A lo
__device__ __half g_Bqh [QKVN * 4096];              // w_qkv^T fp16  [N=6144][K=4096]
__device__ __half g_Boh [4096 * 4096];              // w_o^T  fp16   [N=4096][K=4096]

// fp16 attention operands (Q pre-scaled by 1/sqrt(d), exact hi+lo; K, V single)
__device__ __half g_Qh [BATCH * NH  * S_LEN * HD];  // [b][h][s][d]
__device__ __half g_Ql [BATCH * NH  * S_LEN * HD];
__device__ __half g_Kh [BATCH * NKV * S_LEN * HD];  // [b][kh][s][d]
__device__ __half g_Vh [BATCH * NKV * HD * S_LEN];  // [b][kh][d][s]

// ================= helpers ====================================================
__device__ __forceinline__ uint32_t smem_u32(const void* p) {
    uint32_t a;
    asm("{ .reg .u64 t; cvta.to.shared.u64 t, %1; cvt.u32.u64 %0, t; }" : "=r"(a) : "l"(p));
    return a;
}

#define LDSM_X4(r, addr) \
    asm volatile("ldmatrix.sync.aligned.m8n8.x4.shared.b16 {%0,%1,%2,%3}, [%4];" \
        : "=r"((r)[0]), "=r"((r)[1]), "=r"((r)[2]), "=r"((r)[3]) : "r"(addr))

// fp16 MMA
#define MMAF16(c, a, b0, b1) \
    asm volatile("mma.sync.aligned.m16n8k16.row.col.f32.f16.f16.f32 " \
        "{%0,%1,%2,%3}, {%4,%5,%6,%7}, {%8,%9}, {%0,%1,%2,%3};" \
        : "+f"((c)[0]), "+f"((c)[1]), "+f"((c)[2]), "+f"((c)[3]) \
        : "r"((a)[0]), "r"((a)[1]), "r"((a)[2]), "r"((a)[3]), "r"(b0), "r"(b1))

#define CP_ASYNC16(dst, src) \
    asm volatile("cp.async.cg.shared.global [%0], [%1], 16;" :: "r"(dst), "l"(src))
#define CP_COMMIT() asm volatile("cp.async.commit_group;" ::: "memory")
#define CP_WAIT(n)  asm volatile("cp.async.wait_group %0;" :: "n"(n) : "memory")

__device__ __forceinline__ void split2h(float a, float b, uint32_t& hi, uint32_t& lo) {
    __half ha = __float2half_rn(a), hb = __float2half_rn(b);
    __half la = __float2half_rn(a - __half2float(ha));
    __half lb = __float2half_rn(b - __half2float(hb));
    __half2 H = __halves2half2(ha, hb);
    __half2 L = __halves2half2(la, lb);
    hi = *(uint32_t*)&H;  lo = *(uint32_t*)&L;
}

extern __shared__ char dynsmem[];

// ---------------- inv_freq table ---------------------------------------------
__global__ void init_invfreq_kernel() {
    int i = threadIdx.x;
    if (i < 64) {
        const float LOG2_10000 = 13.28771237954945f;
        g_invfreq[i] = exp2f(-((float)(2 * i) / 128.0f) * LOG2_10000);
    }
}

// ---------------- fp32 -> fp16 hi/lo split (elementwise, float4) --------------
__global__ void __launch_bounds__(256) split_a_kernel(
    const float* __restrict__ X, __half* __restrict__ hi,
    __half* __restrict__ lo, int n4)
{
    int i = blockIdx.x * 256 + threadIdx.x;
    if (i >= n4) return;
    float4 v = ((const float4*)X)[i];
    uint32_t h0, l0, h1, l1;
    split2h(v.x, v.y, h0, l0);
    split2h(v.z, v.w, h1, l1);
    ((uint32_t*)hi)[i * 2]     = h0;
    ((uint32_t*)hi)[i * 2 + 1] = h1;
    ((uint32_t*)lo)[i * 2]     = l0;
    ((uint32_t*)lo)[i * 2 + 1] = l1;
}

// ---------------- W[K,N] fp32 -> Bt[N,K] fp16 (tiled transpose, hi only) ------
__global__ void __launch_bounds__(256) transpose_split_kernel(
    const float* __restrict__ W, __half* __restrict__ bhi, int K, int N)
{
    __shared__ float tile[32][33];
    int tx = threadIdx.x & 31, ty = threadIdx.x >> 5;   // 32 x 8
    int k0 = blockIdx.y * 32, n0 = blockIdx.x * 32;
#pragma unroll
    for (int r = 0; r < 4; r++)
        tile[ty + r * 8][tx] = W[(size_t)(k0 + ty + r * 8) * N + n0 + tx];
    __syncthreads();
#pragma unroll
    for (int r = 0; r < 4; r++) {
        int n = n0 + ty + r * 8;
        int k = k0 + tx;
        bhi[(size_t)n * K + k] = __float2half_rn(tile[tx][ty + r * 8]);
    }
}

// ---------------- mma.sync fp16 2-product GEMM (3-stage, 2 CTAs/SM) -----------
#define GPITCH 80
#define GTSZ   (128 * GPITCH)          // 10240
#define GSTG   (3 * GTSZ)              // 30720 per stage (Ah | Al | Bh)
#define GEMM_SMEM_BYTES (3 * GSTG)     // 92160 -> 2 CTAs = 184320 <= 228KB

__global__ void __launch_bounds__(256, 2) gemm_mma_kernel(
    const __half* __restrict__ Ahi, const __half* __restrict__ Alo,
    const __half* __restrict__ Bh,
    float* __restrict__ C, int Ntot)
{
    const uint32_t sb = smem_u32(dynsmem);
    const int t = threadIdx.x;
    const int wid = t >> 5, lane = t & 31;
    const int bm = blockIdx.y, bn = blockIdx.x;
    const int wm = (wid >> 2) * 64;
    const int wn = (wid & 3) * 32;

    const __half* gsrc[3] = {
        Ahi + (size_t)(bm * 128) * KDIM,
        Alo + (size_t)(bm * 128) * KDIM,
        Bh  + (size_t)(bn * 128) * KDIM };

    const int lrow = t >> 1;
    const int lq   = (t & 1) * 2;

    auto load_chunk = [&](int c, int s) {
        uint32_t base = sb + s * GSTG + lrow * GPITCH + lq * 16;
#pragma unroll
        for (int tens = 0; tens < 3; tens++) {
            const __half* src = gsrc[tens] + (size_t)lrow * KDIM + c * 32 + lq * 8;
            uint32_t d = base + tens * GTSZ;
            CP_ASYNC16(d, src);
            CP_ASYNC16(d + 16, src + 8);
        }
    };

    float acc[4][4][4];
#pragma unroll
    for (int a = 0; a < 4; a++)
#pragma unroll
        for (int b = 0; b < 4; b++)
#pragma unroll
            for (int c = 0; c < 4; c++) acc[a][b][c] = 0.f;

    const int NCH = KDIM / 32;   // 128 chunks

    load_chunk(0, 0);
    CP_COMMIT();
    load_chunk(1, 1);
    CP_COMMIT();

    for (int i = 0; i < NCH; i++) {
        const int s = i % 3;
        if (i + 1 < NCH) CP_WAIT(1); else CP_WAIT(0);
        __syncthreads();
        if (i + 2 < NCH) {
            load_chunk(i + 2, (i + 2) % 3);
            CP_COMMIT();
        }

        const uint32_t sA = sb + s * GSTG;
        const uint32_t sB = sA + 2 * GTSZ;

#pragma unroll
        for (int ks = 0; ks < 2; ks++) {
            const int k0b = ks * 32;
            uint32_t b_hi[2][4];
#pragma unroll
            for (int p = 0; p < 2; p++) {
                uint32_t bd = sB + (uint32_t)(wn + p * 16 + ((lane >> 4) << 3) + (lane & 7)) * GPITCH
                            + k0b + (((lane >> 3) & 1) << 4);
                LDSM_X4(b_hi[p], bd);
            }
#pragma unroll
            for (int mt = 0; mt < 4; mt++) {
                uint32_t ah[4], al[4];
                uint32_t ad = sA + (uint32_t)(wm + mt * 16 + (lane & 15)) * GPITCH
                            + k0b + ((lane >> 4) << 4);
                LDSM_X4(ah, ad);
                LDSM_X4(al, ad + GTSZ);
#pragma unroll
                for (int nt = 0; nt < 4; nt++) {
                    const int p = nt >> 1, hh = (nt & 1) * 2;
                    MMAF16(acc[mt][nt], ah, b_hi[p][hh], b_hi[p][hh + 1]);
                }
#pragma unroll
                for (int nt = 0; nt < 4; nt++) {
                    const int p = nt >> 1, hh = (nt & 1) * 2;
                    MMAF16(acc[mt][nt], al, b_hi[p][hh], b_hi[p][hh + 1]);
                }
            }
        }
    }

#pragma unroll
    for (int mt = 0; mt < 4; mt++)
#pragma unroll
        for (int nt = 0; nt < 4; nt++) {
            int row = bm * 128 + wm + mt * 16 + (lane >> 2);
            int col = bn * 128 + wn + nt * 8 + (lane & 3) * 2;
            float2 v0 = make_float2(acc[mt][nt][0], acc[mt][nt][1]);
            float2 v1 = make_float2(acc[mt][nt][2], acc[mt][nt][3]);
            *(float2*)(C + (size_t)row * Ntot + col)       = v0;
            *(float2*)(C + (size_t)(row + 8) * Ntot + col) = v1;
        }
}

// ---------------- RoPE (NeoX): Q -> SC-scaled fp16 hi/lo ; K -> fp16 ----------
__global__ void rope_split_kernel(const float* __restrict__ qkv,
                                  const int*   __restrict__ positions)
{
    int idx = blockIdx.x * 256 + threadIdx.x;
    int i  = idx & 63;
    int s  = (idx >> 6) & (S_LEN - 1);
    int r  = idx >> 17;          // b*40 + hh
    int hh = r % 40;
    int b  = r / 40;

    float pos = (float)positions[b * S_LEN + s];
    float ang = pos * g_invfreq[i];
    float sn, cs;
    sincosf(ang, &sn, &cs);

    if (hh < 32) {
        const float SC = 0.08838834764831843f;   // 1/sqrt(128), folded into Q
        const float* src = qkv + ((size_t)(b * S_LEN + s)) * QKVN + hh * HD;
        float x1 = src[i], x2 = src[i + 64];
        float y1 = (x1 * cs - x2 * sn) * SC;
        float y2 = (x2 * cs + x1 * sn) * SC;
        size_t base = ((size_t)(b * NH + hh) * S_LEN + s) * HD;
        __half h1 = __float2half_rn(y1);
        __half h2 = __float2half_rn(y2);
        g_Qh[base + i]      = h1;
        g_Qh[base + i + 64] = h2;
        g_Ql[base + i]      = __float2half_rn(y1 - __half2float(h1));
        g_Ql[base + i + 64] = __float2half_rn(y2 - __half2float(h2));
    } else {
        int kh = hh - 32;
        const float* src = qkv + ((size_t)(b * S_LEN + s)) * QKVN + HID + kh * HD;
        float x1 = src[i], x2 = src[i + 64];
        float y1 = x1 * cs - x2 * sn;
        float y2 = x2 * cs + x1 * sn;
        size_t base = ((size_t)(b * NKV + kh) * S_LEN + s) * HD;
        g_Kh[base + i]      = __float2half_rn(y1);
        g_Kh[base + i + 64] = __float2half_rn(y2);
    }
}

// ---------------- V: [s][d] fp32 -> [d][s] fp16 (tiled transpose, hi only) ----
__global__ void __launch_bounds__(256) v_split_kernel(const float* __restrict__ qkv)
{
    __shared__ float tile[32][33];
    int tx = threadIdx.x & 31, ty = threadIdx.x >> 5;   // 32 x 8
    int s0 = blockIdx.x * 32, d0 = blockIdx.y * 32;
    int slab = blockIdx.z;                               // b*NKV + kh
    int b = slab / NKV, kh = slab % NKV;

    const float* src = qkv + (size_t)(b * S_LEN) * QKVN + VOFF + kh * HD;
#pragma unroll
    for (int r = 0; r < 4; r++)
        tile[ty + r * 8][tx] = src[(size_t)(s0 + ty + r * 8) * QKVN + d0 + tx];
    __syncthreads();
#pragma unroll
    for (int r = 0; r < 4; r++) {
        int d = d0 + ty + r * 8;
        int s = s0 + tx;
        size_t o = ((size_t)(b * NKV + kh) * HD + d) * S_LEN + s;
        g_Vh[o] = __float2half_rn(tile[tx][ty + r * 8]);
    }
}

// ---------------- mma.sync fp16 2-product flash attention (R14 design) --------
// 2-stage K/V double buffer, 1 CTA/SM. Q pre-scaled by SC -> no score scaling.
#define AQ_PITCH 272     // 256B row + 16B pad
#define AK_PITCH 272
#define AV_PITCH 144     // 128B row + 16B pad
#define SQ_BYTES (128 * AQ_PITCH)            // 34816
#define SK_BYTES (64  * AK_PITCH)            // 17408
#define SV_BYTES (128 * AV_PITCH)            // 18432
#define KV_STG   (SK_BYTES + SV_BYTES)       // 35840 per stage
#define ATT_SMEM_BYTES (2 * SQ_BYTES + 2 * KV_STG)  // 141312

__global__ void __launch_bounds__(256, 1) attn_mma_kernel(
    __half* __restrict__ Ohi, __half* __restrict__ Olo)
{
    const int qt = blockIdx.x;      // 0..15 (128-row tiles)
    const int h  = blockIdx.y;
    const int b  = blockIdx.z;
    const int kh = h >> 2;

    const uint32_t sb  = smem_u32(dynsmem);
    const uint32_t sQh = sb;
    const uint32_t sQl = sQh + SQ_BYTES;
    const uint32_t sKV = sQl + SQ_BYTES;     // stage base: + s*KV_STG  (Kh | Vh)

    const int t = threadIdx.x;
    const int wid = t >> 5, lane = t & 31;
    const int wm = wid * 16;

    const __half* kb0 = g_Kh + ((size_t)(b * NKV + kh) * S_LEN) * HD;
    const __half* vb0 = g_Vh + ((size_t)(b * NKV + kh) * HD) * S_LEN;

    auto load_kv = [&](int kt, int s) {
        const uint32_t st = sKV + s * KV_STG;
#pragma unroll
        for (int u = 0; u < 4; u++) {
            int id = t + u * 256;            // 1024: 64 rows x 16 chunks (K)
            int row = id >> 4, ch = id & 15;
            CP_ASYNC16(st + row * AK_PITCH + ch * 16,
                       kb0 + (size_t)(kt * 64 + row) * HD + ch * 8);
        }
#pragma unroll
        for (int u = 0; u < 4; u++) {
            int id = t + u * 256;            // 1024: 128 rows x 8 chunks (V)
            int row = id >> 3, ch = id & 7;
            CP_ASYNC16(st + SK_BYTES + row * AV_PITCH + ch * 16,
                       vb0 + (size_t)row * S_LEN + kt * 64 + ch * 8);
        }
    };

    // ---- load Q tile (once) ----
    {
        const __half* q0 = g_Qh + ((size_t)(b * NH + h) * S_LEN + qt * 128) * HD;
        const __half* q1 = g_Ql + ((size_t)(b * NH + h) * S_LEN + qt * 128) * HD;
#pragma unroll
        for (int u = 0; u < 8; u++) {
            int id = t + u * 256;            // 2048 ids: 128 rows x 16 chunks
            int row = id >> 4, ch = id & 15;
            uint32_t d = row * AQ_PITCH + ch * 16;
            CP_ASYNC16(sQh + d, q0 + (size_t)row * HD + ch * 8);
            CP_ASYNC16(sQl + d, q1 + (size_t)row * HD + ch * 8);
        }
        CP_COMMIT();
    }

    float acc[16][4];
#pragma unroll
    for (int n = 0; n < 16; n++)
#pragma unroll
        for (int c = 0; c < 4; c++) acc[n][c] = 0.f;
    float m0 = -1e30f, m1 = -1e30f, l0 = 0.f, l1 = 0.f;

    const int nkt = 2 * qt + 2;

    load_kv(0, 0);
    CP_COMMIT();

    for (int kt = 0; kt < nkt; kt++) {
        const int s = kt & 1;
        CP_WAIT(0);          // tile kt (and Q on iter 0) resident
        __syncthreads();     // orders prev-iter readers of stage s^1
        if (kt + 1 < nkt) {
            load_kv(kt + 1, s ^ 1);
            CP_COMMIT();
        }

        const uint32_t sKh = sKV + s * KV_STG;
        const uint32_t sVh = sKh + SK_BYTES;

        // ---- scores: S = (SC*Q) K^T (64 cols), 2-product (Qh+Ql) x Kh ----
        float sc4[8][4];
#pragma unroll
        for (int n = 0; n < 8; n++)
#pragma unroll
            for (int c = 0; c < 4; c++) sc4[n][c] = 0.f;

#pragma unroll
        for (int dc = 0; dc < 8; dc++) {
            const int k0b = dc * 32;
            uint32_t ah[4], al[4];
            uint32_t qa = sQh + (uint32_t)(wm + (lane & 15)) * AQ_PITCH + k0b + ((lane >> 4) << 4);
            LDSM_X4(ah, qa);
            LDSM_X4(al, qa + SQ_BYTES);
            uint32_t bh[4][4];
#pragma unroll
            for (int p = 0; p < 4; p++) {
                uint32_t ka = sKh + (uint32_t)(p * 16 + ((lane >> 4) << 3) + (lane & 7)) * AK_PITCH
                            + k0b + (((lane >> 3) & 1) << 4);
                LDSM_X4(bh[p], ka);
            }
#pragma unroll
            for (int nt = 0; nt < 8; nt++) {
                const int p = nt >> 1, hh = (nt & 1) * 2;
                MMAF16(sc4[nt], ah, bh[p][hh], bh[p][hh + 1]);
            }
#pragma unroll
            for (int nt = 0; nt < 8; nt++) {
                const int p = nt >> 1, hh = (nt & 1) * 2;
                MMAF16(sc4[nt], al, bh[p][hh], bh[p][hh + 1]);
            }
        }

        // ---- causal mask only (scale already folded into Q) ----
        if (kt >= 2 * qt) {
            const int gr0 = qt * 128 + wm + (lane >> 2);
#pragma unroll
            for (int nt = 0; nt < 8; nt++)
#pragma unroll
                for (int c = 0; c < 4; c++) {
                    int gc = kt * 64 + nt * 8 + ((lane & 3) << 1) + (c & 1);
                    int gr = gr0 + ((c >> 1) << 3);
                    if (gc > gr) sc4[nt][c] = -1e30f;
                }
        }

        // ---- online softmax (two rows per thread; quad shfl) ----
        float mt0 = -1e30f, mt1 = -1e30f;
#pragma unroll
        for (int nt = 0; nt < 8; nt++) {
            mt0 = fmaxf(mt0, fmaxf(sc4[nt][0], sc4[nt][1]));
            mt1 = fmaxf(mt1, fmaxf(sc4[nt][2], sc4[nt][3]));
        }
        mt0 = fmaxf(mt0, __shfl_xor_sync(0xffffffffu, mt0, 1));
        mt0 = fmaxf(mt0, __shfl_xor_sync(0xffffffffu, mt0, 2));
        mt1 = fmaxf(mt1, __shfl_xor_sync(0xffffffffu, mt1, 1));
        mt1 = fmaxf(mt1, __shfl_xor_sync(0xffffffffu, mt1, 2));
        float mn0 = fmaxf(m0, mt0), mn1 = fmaxf(m1, mt1);
        float es0 = __expf(m0 - mn0), es1 = __expf(m1 - mn1);
        float rs0 = 0.f, rs1 = 0.f;
#pragma unroll
        for (int nt = 0; nt < 8; nt++) {
            sc4[nt][0] = __expf(sc4[nt][0] - mn0);
            sc4[nt][1] = __expf(sc4[nt][1] - mn0);
            sc4[nt][2] = __expf(sc4[nt][2] - mn1);
            sc4[nt][3] = __expf(sc4[nt][3] - mn1);
            rs0 += sc4[nt][0] + sc4[nt][1];
            rs1 += sc4[nt][2] + sc4[nt][3];
        }
        rs0 += __shfl_xor_sync(0xffffffffu, rs0, 1);
        rs0 += __shfl_xor_sync(0xffffffffu, rs0, 2);
        rs1 += __shfl_xor_sync(0xffffffffu, rs1, 1);
        rs1 += __shfl_xor_sync(0xffffffffu, rs1, 2);
        l0 = l0 * es0 + rs0;  m0 = mn0;
        l1 = l1 * es1 + rs1;  m1 = mn1;
#pragma unroll
        for (int n = 0; n < 16; n++) {
            acc[n][0] *= es0;  acc[n][1] *= es0;
            acc[n][2] *= es1;  acc[n][3] *= es1;
        }

        // ---- PV: O += P V ; P exact (hi+lo fp16) x Vh ----
#pragma unroll
        for (int kc = 0; kc < 4; kc++) {
            uint32_t ph[4], pl[4];
            split2h(sc4[2 * kc][0],     sc4[2 * kc][1],     ph[0], pl[0]);
            split2h(sc4[2 * kc][2],     sc4[2 * kc][3],     ph[1], pl[1]);
            split2h(sc4[2 * kc + 1][0], sc4[2 * kc + 1][1], ph[2], pl[2]);
            split2h(sc4[2 * kc + 1][2], sc4[2 * kc + 1][3], ph[3], pl[3]);
#pragma unroll
            for (int dp = 0; dp < 8; dp++) {
                uint32_t vh4[4];
                uint32_t va = sVh + (uint32_t)(dp * 16 + ((lane >> 4) << 3) + (lane & 7)) * AV_PITCH
                            + kc * 32 + (((lane >> 3) & 1) << 4);
                LDSM_X4(vh4, va);
                const int n0 = dp * 2, n1 = dp * 2 + 1;
                MMAF16(acc[n0], ph, vh4[0], vh4[1]);
                MMAF16(acc[n1], ph, vh4[2], vh4[3]);
                MMAF16(acc[n0], pl, vh4[0], vh4[1]);
                MMAF16(acc[n1], pl, vh4[2], vh4[3]);
            }
        }
    }

    // ---- epilogue: normalize, split to fp16 hi/lo, write [b*S+s][h*128+d] ----
    const float inv0 = 1.0f / l0, inv1 = 1.0f / l1;
    const size_t row0 = (size_t)(b * S_LEN + qt * 128 + wm + (lane >> 2));
    const int colb = h * HD + ((lane & 3) << 1);
#pragma unroll
    for (int nt = 0; nt < 16; nt++) {
        uint32_t h0, lo0, h1, lo1;
        split2h(acc[nt][0] * inv0, acc[nt][1] * inv0, h0, lo0);
        split2h(acc[nt][2] * inv1, acc[nt][3] * inv1, h1, lo1);
        const size_t o0 = row0 * HID + colb + nt * 8;
        const size_t o1 = (row0 + 8) * HID + colb + nt * 8;
        *(uint32_t*)(Ohi + o0) = h0;
        *(uint32_t*)(Olo + o0) = lo0;
        *(uint32_t*)(Ohi + o1) = h1;
        *(uint32_t*)(Olo + o1) = lo1;
    }
}

// ---------------- launch ------------------------------------------------------
extern "C" void kernel_launch(void* const* d_in, const int* in_sizes, int n_in,
                              void* d_out, int out_size)
{
    const int*   positions = (const int*)  d_in[0];
    const float* hidden    = (const float*)d_in[1];
    const float* w_qkv     = (const float*)d_in[2];
    const float* w_o       = (const float*)d_in[3];
    float*       out       = (float*)d_out;

    static float* qkv_p;
    static __half *ahi, *alo, *bqh, *boh;
    static bool init_done = false;
    if (!init_done) {
        cudaGetSymbolAddress((void**)&qkv_p, g_qkv);
        cudaGetSymbolAddress((void**)&ahi, g_Ahi);
        cudaGetSymbolAddress((void**)&alo, g_Alo);
        cudaGetSymbolAddress((void**)&bqh, g_Bqh);
        cudaGetSymbolAddress((void**)&boh, g_Boh);
        cudaFuncSetAttribute(gemm_mma_kernel,
                             cudaFuncAttributeMaxDynamicSharedMemorySize, GEMM_SMEM_BYTES);
        cudaFuncSetAttribute(attn_mma_kernel,
                             cudaFuncAttributeMaxDynamicSharedMemorySize, ATT_SMEM_BYTES);
        init_done = true;
    }

    const int M = BATCH * S_LEN;   // 4096

    init_invfreq_kernel<<<1, 64>>>();

    // prep: split hidden (fp16 hi/lo), transpose weights (fp16 hi)
    split_a_kernel<<<(M * KDIM / 4 + 255) / 256, 256>>>(hidden, ahi, alo, M * KDIM / 4);
    transpose_split_kernel<<<dim3(QKVN / 32, KDIM / 32), 256>>>(w_qkv, bqh, KDIM, QKVN);
    transpose_split_kernel<<<dim3(HID / 32, KDIM / 32), 256>>>(w_o, boh, KDIM, HID);

    // qkv = hidden @ w_qkv  (fp16 2-product)
    gemm_mma_kernel<<<dim3(QKVN / 128, M / 128), 256, GEMM_SMEM_BYTES>>>(
        ahi, alo, bqh, qkv_p, QKVN);

    // rope + split Q (SC-scaled, exact) / K (single); transpose V (single)
    rope_split_kernel<<<(BATCH * 40 * S_LEN * 64) / 256, 256>>>(qkv_p, positions);
    v_split_kernel<<<dim3(S_LEN / 32, HD / 32, BATCH * NKV), 256>>>(qkv_p);

    // flash attention (fp16 2-product, 2-stage KV); writes fp16 hi/lo into A bufs
    attn_mma_kernel<<<dim3(S_LEN / 128, NH, BATCH), 256, ATT_SMEM_BYTES>>>(ahi, alo);

    // out = attn @ w_o  (fp16 2-product)
    gemm_mma_kernel<<<dim3(HID / 128, M / 128), 256, GEMM_SMEM_BYTES>>>(
        ahi, alo, boh, out, HID);
}

// round 17
// speedup vs baseline: 2.4065x; 1.5347x over previous
#include <cuda_runtime.h>
#include <cuda_bf16.h>
#include <cuda_fp16.h>
#include <cstdint>
#include <math.h>

#define BATCH 2
#define S_LEN 2048
#define HID   4096
#define NH    32
#define NKV   8
#define HD    128
#define QKVN  6144          // Q 4096 | K 1024 | V 1024
#define VOFF  5120          // Q_SIZE + KV_SIZE
#define KDIM  4096          // GEMM K (reduction) for both projections

// ---------------- scratch (no allocation allowed -> device globals) ----------
__device__ float g_qkv [BATCH * S_LEN * QKVN];      // qkv projection output (fp32)
__device__ float g_invfreq[64];

// fp16 operands for the tensor-core GEMMs (single-product: A hi, B hi)
__device__ __half g_Ahi [4096 * 4096];              // A hi (hidden; then attn out)
__device__ __half g_Bqh [QKVN * 4096];              // w_qkv^T fp16  [N=6144][K=4096]
__device__ __half g_Boh [4096 * 4096];              // w_o^T  fp16   [N=4096][K=4096]

// fp16 attention operands (Q pre-scaled by 1/sqrt(d), exact hi+lo; K, V single)
__device__ __half g_Qh [BATCH * NH  * S_LEN * HD];  // [b][h][s][d]
__device__ __half g_Ql [BATCH * NH  * S_LEN * HD];
__device__ __half g_Kh [BATCH * NKV * S_LEN * HD];  // [b][kh][s][d]
__device__ __half g_Vh [BATCH * NKV * HD * S_LEN];  // [b][kh][d][s]

// ================= helpers ====================================================
__device__ __forceinline__ uint32_t smem_u32(const void* p) {
    uint32_t a;
    asm("{ .reg .u64 t; cvta.to.shared.u64 t, %1; cvt.u32.u64 %0, t; }" : "=r"(a) : "l"(p));
    return a;
}

#define LDSM_X4(r, addr) \
    asm volatile("ldmatrix.sync.aligned.m8n8.x4.shared.b16 {%0,%1,%2,%3}, [%4];" \
        : "=r"((r)[0]), "=r"((r)[1]), "=r"((r)[2]), "=r"((r)[3]) : "r"(addr))

// fp16 MMA
#define MMAF16(c, a, b0, b1) \
    asm volatile("mma.sync.aligned.m16n8k16.row.col.f32.f16.f16.f32 " \
        "{%0,%1,%2,%3}, {%4,%5,%6,%7}, {%8,%9}, {%0,%1,%2,%3};" \
        : "+f"((c)[0]), "+f"((c)[1]), "+f"((c)[2]), "+f"((c)[3]) \
        : "r"((a)[0]), "r"((a)[1]), "r"((a)[2]), "r"((a)[3]), "r"(b0), "r"(b1))

#define CP_ASYNC16(dst, src) \
    asm volatile("cp.async.cg.shared.global [%0], [%1], 16;" :: "r"(dst), "l"(src))
#define CP_COMMIT() asm volatile("cp.async.commit_group;" ::: "memory")
#define CP_WAIT(n)  asm volatile("cp.async.wait_group %0;" :: "n"(n) : "memory")

__device__ __forceinline__ void split2h(float a, float b, uint32_t& hi, uint32_t& lo) {
    __half ha = __float2half_rn(a), hb = __float2half_rn(b);
    __half la = __float2half_rn(a - __half2float(ha));
    __half lb = __float2half_rn(b - __half2float(hb));
    __half2 H = __halves2half2(ha, hb);
    __half2 L = __halves2half2(la, lb);
    hi = *(uint32_t*)&H;  lo = *(uint32_t*)&L;
}

extern __shared__ char dynsmem[];

// ---------------- inv_freq table ---------------------------------------------
__global__ void init_invfreq_kernel() {
    int i = threadIdx.x;
    if (i < 64) {
        const float LOG2_10000 = 13.28771237954945f;
        g_invfreq[i] = exp2f(-((float)(2 * i) / 128.0f) * LOG2_10000);
    }
}

// ---------------- fp32 -> fp16 (elementwise, float4) --------------------------
__global__ void __launch_bounds__(256) split_a_kernel(
    const float* __restrict__ X, __half* __restrict__ hi, int n4)
{
    int i = blockIdx.x * 256 + threadIdx.x;
    if (i >= n4) return;
    float4 v = ((const float4*)X)[i];
    __half2 h0 = __halves2half2(__float2half_rn(v.x), __float2half_rn(v.y));
    __half2 h1 = __halves2half2(__float2half_rn(v.z), __float2half_rn(v.w));
    ((uint32_t*)hi)[i * 2]     = *(uint32_t*)&h0;
    ((uint32_t*)hi)[i * 2 + 1] = *(uint32_t*)&h1;
}

// ---------------- W[K,N] fp32 -> Bt[N,K] fp16 (tiled transpose) ---------------
__global__ void __launch_bounds__(256) transpose_split_kernel(
    const float* __restrict__ W, __half* __restrict__ bhi, int K, int N)
{
    __shared__ float tile[32][33];
    int tx = threadIdx.x & 31, ty = threadIdx.x >> 5;   // 32 x 8
    int k0 = blockIdx.y * 32, n0 = blockIdx.x * 32;
#pragma unroll
    for (int r = 0; r < 4; r++)
        tile[ty + r * 8][tx] = W[(size_t)(k0 + ty + r * 8) * N + n0 + tx];
    __syncthreads();
#pragma unroll
    for (int r = 0; r < 4; r++) {
        int n = n0 + ty + r * 8;
        int k = k0 + tx;
        bhi[(size_t)n * K + k] = __float2half_rn(tile[tx][ty + r * 8]);
    }
}

// ---------------- mma.sync fp16 single-product GEMM (3-stage, 2 CTAs/SM) ------
// C = fl16(A) @ fl16(W); fp32 accumulate. Error ~1e-4 relative (random-walk).
#define GPITCH 80
#define GTSZ   (128 * GPITCH)          // 10240
#define GSTG   (2 * GTSZ)              // 20480 per stage (Ah | Bh)
#define GEMM_SMEM_BYTES (3 * GSTG)     // 61440 -> 2 CTAs = 122880 <= 228KB

__global__ void __launch_bounds__(256, 2) gemm_mma_kernel(
    const __half* __restrict__ Ahi, const __half* __restrict__ Bh,
    float* __restrict__ C, int Ntot)
{
    const uint32_t sb = smem_u32(dynsmem);
    const int t = threadIdx.x;
    const int wid = t >> 5, lane = t & 31;
    const int bm = blockIdx.y, bn = blockIdx.x;
    const int wm = (wid >> 2) * 64;
    const int wn = (wid & 3) * 32;

    const __half* gsrc[2] = {
        Ahi + (size_t)(bm * 128) * KDIM,
        Bh  + (size_t)(bn * 128) * KDIM };

    const int lrow = t >> 1;
    const int lq   = (t & 1) * 2;

    auto load_chunk = [&](int c, int s) {
        uint32_t base = sb + s * GSTG + lrow * GPITCH + lq * 16;
#pragma unroll
        for (int tens = 0; tens < 2; tens++) {
            const __half* src = gsrc[tens] + (size_t)lrow * KDIM + c * 32 + lq * 8;
            uint32_t d = base + tens * GTSZ;
            CP_ASYNC16(d, src);
            CP_ASYNC16(d + 16, src + 8);
        }
    };

    float acc[4][4][4];
#pragma unroll
    for (int a = 0; a < 4; a++)
#pragma unroll
        for (int b = 0; b < 4; b++)
#pragma unroll
            for (int c = 0; c < 4; c++) acc[a][b][c] = 0.f;

    const int NCH = KDIM / 32;   // 128 chunks

    load_chunk(0, 0);
    CP_COMMIT();
    load_chunk(1, 1);
    CP_COMMIT();

    for (int i = 0; i < NCH; i++) {
        const int s = i % 3;
        if (i + 1 < NCH) CP_WAIT(1); else CP_WAIT(0);
        __syncthreads();
        if (i + 2 < NCH) {
            load_chunk(i + 2, (i + 2) % 3);
            CP_COMMIT();
        }

        const uint32_t sA = sb + s * GSTG;
        const uint32_t sB = sA + GTSZ;

#pragma unroll
        for (int ks = 0; ks < 2; ks++) {
            const int k0b = ks * 32;
            uint32_t b_hi[2][4];
#pragma unroll
            for (int p = 0; p < 2; p++) {
                uint32_t bd = sB + (uint32_t)(wn + p * 16 + ((lane >> 4) << 3) + (lane & 7)) * GPITCH
                            + k0b + (((lane >> 3) & 1) << 4);
                LDSM_X4(b_hi[p], bd);
            }
#pragma unroll
            for (int mt = 0; mt < 4; mt++) {
                uint32_t ah[4];
                uint32_t ad = sA + (uint32_t)(wm + mt * 16 + (lane & 15)) * GPITCH
                            + k0b + ((lane >> 4) << 4);
                LDSM_X4(ah, ad);
#pragma unroll
                for (int nt = 0; nt < 4; nt++) {
                    const int p = nt >> 1, hh = (nt & 1) * 2;
                    MMAF16(acc[mt][nt], ah, b_hi[p][hh], b_hi[p][hh + 1]);
                }
            }
        }
    }

#pragma unroll
    for (int mt = 0; mt < 4; mt++)
#pragma unroll
        for (int nt = 0; nt < 4; nt++) {
            int row = bm * 128 + wm + mt * 16 + (lane >> 2);
            int col = bn * 128 + wn + nt * 8 + (lane & 3) * 2;
            float2 v0 = make_float2(acc[mt][nt][0], acc[mt][nt][1]);
            float2 v1 = make_float2(acc[mt][nt][2], acc[mt][nt][3]);
            *(float2*)(C + (size_t)row * Ntot + col)       = v0;
            *(float2*)(C + (size_t)(row + 8) * Ntot + col) = v1;
        }
}

// ---------------- RoPE (NeoX): Q -> SC-scaled fp16 hi/lo ; K -> fp16 ----------
__global__ void rope_split_kernel(const float* __restrict__ qkv,
                                  const int*   __restrict__ positions)
{
    int idx = blockIdx.x * 256 + threadIdx.x;
    int i  = idx & 63;
    int s  = (idx >> 6) & (S_LEN - 1);
    int r  = idx >> 17;          // b*40 + hh
    int hh = r % 40;
    int b  = r / 40;

    float pos = (float)positions[b * S_LEN + s];
    float ang = pos * g_invfreq[i];
    float sn, cs;
    sincosf(ang, &sn, &cs);

    if (hh < 32) {
        const float SC = 0.08838834764831843f;   // 1/sqrt(128), folded into Q
        const float* src = qkv + ((size_t)(b * S_LEN + s)) * QKVN + hh * HD;
        float x1 = src[i], x2 = src[i + 64];
        float y1 = (x1 * cs - x2 * sn) * SC;
        float y2 = (x2 * cs + x1 * sn) * SC;
        size_t base = ((size_t)(b * NH + hh) * S_LEN + s) * HD;
        __half h1 = __float2half_rn(y1);
        __half h2 = __float2half_rn(y2);
        g_Qh[base + i]      = h1;
        g_Qh[base + i + 64] = h2;
        g_Ql[base + i]      = __float2half_rn(y1 - __half2float(h1));
        g_Ql[base + i + 64] = __float2half_rn(y2 - __half2float(h2));
    } else {
        int kh = hh - 32;
        const float* src = qkv + ((size_t)(b * S_LEN + s)) * QKVN + HID + kh * HD;
        float x1 = src[i], x2 = src[i + 64];
        float y1 = x1 * cs - x2 * sn;
        float y2 = x2 * cs + x1 * sn;
        size_t base = ((size_t)(b * NKV + kh) * S_LEN + s) * HD;
        g_Kh[base + i]      = __float2half_rn(y1);
        g_Kh[base + i + 64] = __float2half_rn(y2);
    }
}

// ---------------- V: [s][d] fp32 -> [d][s] fp16 (tiled transpose) -------------
__global__ void __launch_bounds__(256) v_split_kernel(const float* __restrict__ qkv)
{
    __shared__ float tile[32][33];
    int tx = threadIdx.x & 31, ty = threadIdx.x >> 5;   // 32 x 8
    int s0 = blockIdx.x * 32, d0 = blockIdx.y * 32;
    int slab = blockIdx.z;                               // b*NKV + kh
    int b = slab / NKV, kh = slab % NKV;

    const float* src = qkv + (size_t)(b * S_LEN) * QKVN + VOFF + kh * HD;
#pragma unroll
    for (int r = 0; r < 4; r++)
        tile[ty + r * 8][tx] = src[(size_t)(s0 + ty + r * 8) * QKVN + d0 + tx];
    __syncthreads();
#pragma unroll
    for (int r = 0; r < 4; r++) {
        int d = d0 + ty + r * 8;
        int s = s0 + tx;
        size_t o = ((size_t)(b * NKV + kh) * HD + d) * S_LEN + s;
        g_Vh[o] = __float2half_rn(tile[tx][ty + r * 8]);
    }
}

// ---------------- mma.sync fp16 2-product flash attention (unchanged) ---------
// 2-stage K/V double buffer, 1 CTA/SM. Q pre-scaled by SC -> no score scaling.
#define AQ_PITCH 272     // 256B row + 16B pad
#define AK_PITCH 272
#define AV_PITCH 144     // 128B row + 16B pad
#define SQ_BYTES (128 * AQ_PITCH)            // 34816
#define SK_BYTES (64  * AK_PITCH)            // 17408
#define SV_BYTES (128 * AV_PITCH)            // 18432
#define KV_STG   (SK_BYTES + SV_BYTES)       // 35840 per stage
#define ATT_SMEM_BYTES (2 * SQ_BYTES + 2 * KV_STG)  // 141312

__global__ void __launch_bounds__(256, 1) attn_mma_kernel(__half* __restrict__ Ohi)
{
    const int qt = blockIdx.x;      // 0..15 (128-row tiles)
    const int h  = blockIdx.y;
    const int b  = blockIdx.z;
    const int kh = h >> 2;

    const uint32_t sb  = smem_u32(dynsmem);
    const uint32_t sQh = sb;
    const uint32_t sQl = sQh + SQ_BYTES;
    const uint32_t sKV = sQl + SQ_BYTES;     // stage base: + s*KV_STG  (Kh | Vh)

    const int t = threadIdx.x;
    const int wid = t >> 5, lane = t & 31;
    const int wm = wid * 16;

    const __half* kb0 = g_Kh + ((size_t)(b * NKV + kh) * S_LEN) * HD;
    const __half* vb0 = g_Vh + ((size_t)(b * NKV + kh) * HD) * S_LEN;

    auto load_kv = [&](int kt, int s) {
        const uint32_t st = sKV + s * KV_STG;
#pragma unroll
        for (int u = 0; u < 4; u++) {
            int id = t + u * 256;            // 1024: 64 rows x 16 chunks (K)
            int row = id >> 4, ch = id & 15;
            CP_ASYNC16(st + row * AK_PITCH + ch * 16,
                       kb0 + (size_t)(kt * 64 + row) * HD + ch * 8);
        }
#pragma unroll
        for (int u = 0; u < 4; u++) {
            int id = t + u * 256;            // 1024: 128 rows x 8 chunks (V)
            int row = id >> 3, ch = id & 7;
            CP_ASYNC16(st + SK_BYTES + row * AV_PITCH + ch * 16,
                       vb0 + (size_t)row * S_LEN + kt * 64 + ch * 8);
        }
    };

    // ---- load Q tile (once) ----
    {
        const __half* q0 = g_Qh + ((size_t)(b * NH + h) * S_LEN + qt * 128) * HD;
        const __half* q1 = g_Ql + ((size_t)(b * NH + h) * S_LEN + qt * 128) * HD;
#pragma unroll
        for (int u = 0; u < 8; u++) {
            int id = t + u * 256;            // 2048 ids: 128 rows x 16 chunks
            int row = id >> 4, ch = id & 15;
            uint32_t d = row * AQ_PITCH + ch * 16;
            CP_ASYNC16(sQh + d, q0 + (size_t)row * HD + ch * 8);
            CP_ASYNC16(sQl + d, q1 + (size_t)row * HD + ch * 8);
        }
        CP_COMMIT();
    }

    float acc[16][4];
#pragma unroll
    for (int n = 0; n < 16; n++)
#pragma unroll
        for (int c = 0; c < 4; c++) acc[n][c] = 0.f;
    float m0 = -1e30f, m1 = -1e30f, l0 = 0.f, l1 = 0.f;

    const int nkt = 2 * qt + 2;

    load_kv(0, 0);
    CP_COMMIT();

    for (int kt = 0; kt < nkt; kt++) {
        const int s = kt & 1;
        CP_WAIT(0);          // tile kt (and Q on iter 0) resident
        __syncthreads();     // orders prev-iter readers of stage s^1
        if (kt + 1 < nkt) {
            load_kv(kt + 1, s ^ 1);
            CP_COMMIT();
        }

        const uint32_t sKh = sKV + s * KV_STG;
        const uint32_t sVh = sKh + SK_BYTES;

        // ---- scores: S = (SC*Q) K^T (64 cols), 2-product (Qh+Ql) x Kh ----
        float sc4[8][4];
#pragma unroll
        for (int n = 0; n < 8; n++)
#pragma unroll
            for (int c = 0; c < 4; c++) sc4[n][c] = 0.f;

#pragma unroll
        for (int dc = 0; dc < 8; dc++) {
            const int k0b = dc * 32;
            uint32_t ah[4], al[4];
            uint32_t qa = sQh + (uint32_t)(wm + (lane & 15)) * AQ_PITCH + k0b + ((lane >> 4) << 4);
            LDSM_X4(ah, qa);
            LDSM_X4(al, qa + SQ_BYTES);
            uint32_t bh[4][4];
#pragma unroll
            for (int p = 0; p < 4; p++) {
                uint32_t ka = sKh + (uint32_t)(p * 16 + ((lane >> 4) << 3) + (lane & 7)) * AK_PITCH
                            + k0b + (((lane >> 3) & 1) << 4);
                LDSM_X4(bh[p], ka);
            }
#pragma unroll
            for (int nt = 0; nt < 8; nt++) {
                const int p = nt >> 1, hh = (nt & 1) * 2;
                MMAF16(sc4[nt], ah, bh[p][hh], bh[p][hh + 1]);
            }
#pragma unroll
            for (int nt = 0; nt < 8; nt++) {
                const int p = nt >> 1, hh = (nt & 1) * 2;
                MMAF16(sc4[nt], al, bh[p][hh], bh[p][hh + 1]);
            }
        }

        // ---- causal mask only (scale already folded into Q) ----
        if (kt >= 2 * qt) {
            const int gr0 = qt * 128 + wm + (lane >> 2);
#pragma unroll
            for (int nt = 0; nt < 8; nt++)
#pragma unroll
                for (int c = 0; c < 4; c++) {
                    int gc = kt * 64 + nt * 8 + ((lane & 3) << 1) + (c & 1);
                    int gr = gr0 + ((c >> 1) << 3);
                    if (gc > gr) sc4[nt][c] = -1e30f;
                }
        }

        // ---- online softmax (two rows per thread; quad shfl) ----
        float mt0 = -1e30f, mt1 = -1e30f;
#pragma unroll
        for (int nt = 0; nt < 8; nt++) {
            mt0 = fmaxf(mt0, fmaxf(sc4[nt][0], sc4[nt][1]));
            mt1 = fmaxf(mt1, fmaxf(sc4[nt][2], sc4[nt][3]));
        }
        mt0 = fmaxf(mt0, __shfl_xor_sync(0xffffffffu, mt0, 1));
        mt0 = fmaxf(mt0, __shfl_xor_sync(0xffffffffu, mt0, 2));
        mt1 = fmaxf(mt1, __shfl_xor_sync(0xffffffffu, mt1, 1));
        mt1 = fmaxf(mt1, __shfl_xor_sync(0xffffffffu, mt1, 2));
        float mn0 = fmaxf(m0, mt0), mn1 = fmaxf(m1, mt1);
        float es0 = __expf(m0 - mn0), es1 = __expf(m1 - mn1);
        float rs0 = 0.f, rs1 = 0.f;
#pragma unroll
        for (int nt = 0; nt < 8; nt++) {
            sc4[nt][0] = __expf(sc4[nt][0] - mn0);
            sc4[nt][1] = __expf(sc4[nt][1] - mn0);
            sc4[nt][2] = __expf(sc4[nt][2] - mn1);
            sc4[nt][3] = __expf(sc4[nt][3] - mn1);
            rs0 += sc4[nt][0] + sc4[nt][1];
            rs1 += sc4[nt][2] + sc4[nt][3];
        }
        rs0 += __shfl_xor_sync(0xffffffffu, rs0, 1);
        rs0 += __shfl_xor_sync(0xffffffffu, rs0, 2);
        rs1 += __shfl_xor_sync(0xffffffffu, rs1, 1);
        rs1 += __shfl_xor_sync(0xffffffffu, rs1, 2);
        l0 = l0 * es0 + rs0;  m0 = mn0;
        l1 = l1 * es1 + rs1;  m1 = mn1;
#pragma unroll
        for (int n = 0; n < 16; n++) {
            acc[n][0] *= es0;  acc[n][1] *= es0;
            acc[n][2] *= es1;  acc[n][3] *= es1;
        }

        // ---- PV: O += P V ; P exact (hi+lo fp16) x Vh ----
#pragma unroll
        for (int kc = 0; kc < 4; kc++) {
            uint32_t ph[4], pl[4];
            split2h(sc4[2 * kc][0],     sc4[2 * kc][1],     ph[0], pl[0]);
            split2h(sc4[2 * kc][2],     sc4[2 * kc][3],     ph[1], pl[1]);
            split2h(sc4[2 * kc + 1][0], sc4[2 * kc + 1][1], ph[2], pl[2]);
            split2h(sc4[2 * kc + 1][2], sc4[2 * kc + 1][3], ph[3], pl[3]);
#pragma unroll
            for (int dp = 0; dp < 8; dp++) {
                uint32_t vh4[4];
                uint32_t va = sVh + (uint32_t)(dp * 16 + ((lane >> 4) << 3) + (lane & 7)) * AV_PITCH
                            + kc * 32 + (((lane >> 3) & 1) << 4);
                LDSM_X4(vh4, va);
                const int n0 = dp * 2, n1 = dp * 2 + 1;
                MMAF16(acc[n0], ph, vh4[0], vh4[1]);
                MMAF16(acc[n1], ph, vh4[2], vh4[3]);
                MMAF16(acc[n0], pl, vh4[0], vh4[1]);
                MMAF16(acc[n1], pl, vh4[2], vh4[3]);
            }
        }
    }

    // ---- epilogue: normalize, round to fp16, write [b*S+s][h*128+d] ----------
    const float inv0 = 1.0f / l0, inv1 = 1.0f / l1;
    const size_t row0 = (size_t)(b * S_LEN + qt * 128 + wm + (lane >> 2));
    const int colb = h * HD + ((lane & 3) << 1);
#pragma unroll
    for (int nt = 0; nt < 16; nt++) {
        __half2 h0 = __halves2half2(__float2half_rn(acc[nt][0] * inv0),
                                    __float2half_rn(acc[nt][1] * inv0));
        __half2 h1 = __halves2half2(__float2half_rn(acc[nt][2] * inv1),
                                    __float2half_rn(acc[nt][3] * inv1));
        *(uint32_t*)(Ohi + row0 * HID + colb + nt * 8)       = *(uint32_t*)&h0;
        *(uint32_t*)(Ohi + (row0 + 8) * HID + colb + nt * 8) = *(uint32_t*)&h1;
    }
}

// ---------------- launch ------------------------------------------------------
extern "C" void kernel_launch(void* const* d_in, const int* in_sizes, int n_in,
                              void* d_out, int out_size)
{
    const int*   positions = (const int*)  d_in[0];
    const float* hidden    = (const float*)d_in[1];
    const float* w_qkv     = (const float*)d_in[2];
    const float* w_o       = (const float*)d_in[3];
    float*       out       = (float*)d_out;

    static float* qkv_p;
    static __half *ahi, *bqh, *boh;
    static bool init_done = false;
    if (!init_done) {
        cudaGetSymbolAddress((void**)&qkv_p, g_qkv);
        cudaGetSymbolAddress((void**)&ahi, g_Ahi);
        cudaGetSymbolAddress((void**)&bqh, g_Bqh);
        cudaGetSymbolAddress((void**)&boh, g_Boh);
        cudaFuncSetAttribute(gemm_mma_kernel,
                             cudaFuncAttributeMaxDynamicSharedMemorySize, GEMM_SMEM_BYTES);
        cudaFuncSetAttribute(attn_mma_kernel,
                             cudaFuncAttributeMaxDynamicSharedMemorySize, ATT_SMEM_BYTES);
        init_done = true;
    }

    const int M = BATCH * S_LEN;   // 4096

    init_invfreq_kernel<<<1, 64>>>();

    // prep: round hidden to fp16, transpose weights to fp16
    split_a_kernel<<<(M * KDIM / 4 + 255) / 256, 256>>>(hidden, ahi, M * KDIM / 4);
    transpose_split_kernel<<<dim3(QKVN / 32, KDIM / 32), 256>>>(w_qkv, bqh, KDIM, QKVN);
    transpose_split_kernel<<<dim3(HID / 32, KDIM / 32), 256>>>(w_o, boh, KDIM, HID);

    // qkv = hidden @ w_qkv  (fp16 single-product)
    gemm_mma_kernel<<<dim3(QKVN / 128, M / 128), 256, GEMM_SMEM_BYTES>>>(
        ahi, bqh, qkv_p, QKVN);

    // rope + split Q (SC-scaled, exact) / K (single); transpose V (single)
    rope_split_kernel<<<(BATCH * 40 * S_LEN * 64) / 256, 256>>>(qkv_p, positions);
    v_split_kernel<<<dim3(S_LEN / 32, HD / 32, BATCH * NKV), 256>>>(qkv_p);

    // flash attention (fp16 2-product); writes fp16 into GEMM-A buf
    attn_mma_kernel<<<dim3(S_LEN / 128, NH, BATCH), 256, ATT_SMEM_BYTES>>>(ahi);

    // out = attn @ w_o  (fp16 single-product)
    gemm_mma_kernel<<<dim3(HID / 128, M / 128), 256, GEMM_SMEM_BYTES>>>(
        ahi, boh, out, HID);
}